// round 2
// baseline (speedup 1.0000x reference)
#include <cuda_runtime.h>

// Problem constants
static constexpr int NR = 128;    // rows (attention mixes over this axis)
static constexpr int NC = 256;    // cols
static constexpr int NE = 768;    // embed
static constexpr int NH = 12;     // heads
static constexpr int ND = 64;     // head dim
static constexpr int NTOK = NR * NC;          // 32768 tokens
static constexpr int OUT_ELEMS = NTOK * NE;   // 25165824
static constexpr float SCALING = 0.125f;      // 1/sqrt(64)

// Scratch (allocation-free rule: __device__ globals)
__device__ float g_q[NTOK * NE];
__device__ float g_k[NTOK * NE];
__device__ float g_v[NTOK * NE];
__device__ float g_c[NTOK * NE];

// ---------------------------------------------------------------------------
// GEMM: out[m][n] = scale * ( sum_k X[m][k] * W[n][k] + bias[n] )
// M=32768, N=768, K=768. Both X and W are K-contiguous (NT layout).
// BM=128, BN=64, BK=16, 256 threads, 8x4 register tile per thread.
// out_sel: 0->g_q, 1->g_k, 2->g_v, 3->use 'out' param
// in_sel : 0->use 'X' param, 1->g_c
// ---------------------------------------------------------------------------
__global__ __launch_bounds__(256) void gemm_bias_kernel(
    const float* __restrict__ X, const float* __restrict__ W,
    const float* __restrict__ bias, float* __restrict__ out,
    float scale, int out_sel, int in_sel)
{
    if (in_sel == 1) X = g_c;
    if (out_sel == 0) out = g_q;
    else if (out_sel == 1) out = g_k;
    else if (out_sel == 2) out = g_v;

    __shared__ float Xs[16][128];   // [k][m] transposed
    __shared__ float Ws[16][64];    // [k][n] transposed

    const int tid = threadIdx.x;
    const int tx = tid & 15;        // -> n
    const int ty = tid >> 4;        // -> m
    const int bm = blockIdx.x * 128;
    const int bn = blockIdx.y * 64;

    float acc[8][4];
    #pragma unroll
    for (int i = 0; i < 8; i++)
        #pragma unroll
        for (int j = 0; j < 4; j++) acc[i][j] = 0.0f;

    for (int k0 = 0; k0 < NE; k0 += 16) {
        // load X tile: 128 rows x 16 k = 512 float4, 2 per thread
        #pragma unroll
        for (int t = 0; t < 2; t++) {
            int f = tid + t * 256;
            int m = f >> 2, u = f & 3;
            float4 xv = *(const float4*)&X[(size_t)(bm + m) * NE + k0 + u * 4];
            Xs[u * 4 + 0][m] = xv.x;
            Xs[u * 4 + 1][m] = xv.y;
            Xs[u * 4 + 2][m] = xv.z;
            Xs[u * 4 + 3][m] = xv.w;
        }
        // load W tile: 64 rows x 16 k = 256 float4, 1 per thread
        {
            int m = tid >> 2, u = tid & 3;
            float4 wv = *(const float4*)&W[(size_t)(bn + m) * NE + k0 + u * 4];
            Ws[u * 4 + 0][m] = wv.x;
            Ws[u * 4 + 1][m] = wv.y;
            Ws[u * 4 + 2][m] = wv.z;
            Ws[u * 4 + 3][m] = wv.w;
        }
        __syncthreads();

        #pragma unroll
        for (int kk = 0; kk < 16; kk++) {
            float4 a0 = *(const float4*)&Xs[kk][ty * 8];
            float4 a1 = *(const float4*)&Xs[kk][ty * 8 + 4];
            float4 b0 = *(const float4*)&Ws[kk][tx * 4];
            float a[8] = {a0.x, a0.y, a0.z, a0.w, a1.x, a1.y, a1.z, a1.w};
            float b[4] = {b0.x, b0.y, b0.z, b0.w};
            #pragma unroll
            for (int i = 0; i < 8; i++)
                #pragma unroll
                for (int j = 0; j < 4; j++)
                    acc[i][j] += a[i] * b[j];
        }
        __syncthreads();
    }

    // epilogue: bias + scale, float4 stores
    const int n = bn + tx * 4;
    float4 bv = *(const float4*)&bias[n];
    #pragma unroll
    for (int i = 0; i < 8; i++) {
        int m = bm + ty * 8 + i;
        float4 ov;
        ov.x = scale * (acc[i][0] + bv.x);
        ov.y = scale * (acc[i][1] + bv.y);
        ov.z = scale * (acc[i][2] + bv.z);
        ov.w = scale * (acc[i][3] + bv.w);
        *(float4*)&out[(size_t)m * NE + n] = ov;
    }
}

// ---------------------------------------------------------------------------
// Attention: one block per (col c, head h). 128 threads, thread i = query row i.
// Dynamic smem: ks[128*64] | vs[128*64] | Ps[128*129]
// ---------------------------------------------------------------------------
__global__ __launch_bounds__(128) void attn_kernel(
    const unsigned char* __restrict__ mask, float* __restrict__ probs_out,
    int write_probs)
{
    extern __shared__ float sm[];
    float* ks = sm;                 // [128][64]
    float* vs = sm + 128 * 64;      // [128][64]
    float* Ps = sm + 2 * 128 * 64;  // [128][129]  (pad 1 -> conflict-free)
    __shared__ unsigned char msk[128];

    const int c = blockIdx.x;
    const int h = blockIdx.y;
    const int tid = threadIdx.x;
    const int i = tid;

    // mask[b=0][j][c]  (all-false in this dataset, applied anyway)
    msk[tid] = mask[tid * NC + c];

    // cooperative K/V tile load (coalesced: 16 threads cover one 64-float row)
    for (int f = tid; f < 128 * 16; f += 128) {
        int j = f >> 4, u = f & 15;
        size_t g = ((size_t)(j * NC + c)) * NE + h * ND + u * 4;
        *(float4*)&ks[j * 64 + u * 4] = *(const float4*)&g_k[g];
        *(float4*)&vs[j * 64 + u * 4] = *(const float4*)&g_v[g];
    }

    // q row i -> registers
    float4 q4[16];
    {
        size_t g = ((size_t)(i * NC + c)) * NE + h * ND;
        #pragma unroll
        for (int u = 0; u < 16; u++)
            q4[u] = *(const float4*)&g_q[g + u * 4];
    }
    __syncthreads();

    // scores row i + running max
    float maxv = -1e30f;
    for (int j = 0; j < 128; j++) {
        float acc = 0.0f;
        #pragma unroll
        for (int u = 0; u < 16; u++) {
            float4 kv = *(const float4*)&ks[j * 64 + u * 4];
            acc += q4[u].x * kv.x + q4[u].y * kv.y
                 + q4[u].z * kv.z + q4[u].w * kv.w;
        }
        if (msk[j]) acc = -10000.0f;
        Ps[i * 129 + j] = acc;
        maxv = fmaxf(maxv, acc);
    }

    // softmax (normalize in place)
    float sum = 0.0f;
    for (int j = 0; j < 128; j++) {
        float e = __expf(Ps[i * 129 + j] - maxv);
        Ps[i * 129 + j] = e;
        sum += e;
    }
    float inv = 1.0f / sum;
    for (int j = 0; j < 128; j++) Ps[i * 129 + j] *= inv;

    __syncthreads();  // all rows of Ps final

    // cooperative coalesced probs write: probs[h][c][0][row][j]
    if (write_probs) {
        float* dst = probs_out + ((size_t)(h * NC + c)) * NR * NR;
        for (int f = tid; f < 128 * 32; f += 128) {
            int row = f >> 5, u = f & 31;
            const float* src = &Ps[row * 129 + u * 4];
            float4 pv = make_float4(src[0], src[1], src[2], src[3]);
            *(float4*)&dst[row * 128 + u * 4] = pv;
        }
    }

    // PV: c[i][c][h][d] = sum_j P[i][j] * v[j][d]
    float4 a4[16];
    #pragma unroll
    for (int u = 0; u < 16; u++) a4[u] = make_float4(0.f, 0.f, 0.f, 0.f);
    for (int j = 0; j < 128; j++) {
        float p = Ps[i * 129 + j];
        #pragma unroll
        for (int u = 0; u < 16; u++) {
            float4 vv = *(const float4*)&vs[j * 64 + u * 4];
            a4[u].x += p * vv.x; a4[u].y += p * vv.y;
            a4[u].z += p * vv.z; a4[u].w += p * vv.w;
        }
    }
    {
        size_t g = ((size_t)(i * NC + c)) * NE + h * ND;
        #pragma unroll
        for (int u = 0; u < 16; u++)
            *(float4*)&g_c[g + u * 4] = a4[u];
    }
}

// ---------------------------------------------------------------------------
extern "C" void kernel_launch(void* const* d_in, const int* in_sizes, int n_in,
                              void* d_out, int out_size)
{
    const float* x          = (const float*)d_in[0];
    const unsigned char* pm = (const unsigned char*)d_in[1];
    const float* Wq = (const float*)d_in[2];
    const float* bq = (const float*)d_in[3];
    const float* Wk = (const float*)d_in[4];
    const float* bk = (const float*)d_in[5];
    const float* Wv = (const float*)d_in[6];
    const float* bv = (const float*)d_in[7];
    const float* Wo = (const float*)d_in[8];
    const float* bo = (const float*)d_in[9];
    float* out = (float*)d_out;

    const int write_probs = (out_size > OUT_ELEMS) ? 1 : 0;
    float* probs_out = out + OUT_ELEMS;

    dim3 ggrid(NTOK / 128, NE / 64);
    // Q (with 1/sqrt(dk) folded in), K, V projections
    gemm_bias_kernel<<<ggrid, 256>>>(x, Wq, bq, nullptr, SCALING, 0, 0);
    gemm_bias_kernel<<<ggrid, 256>>>(x, Wk, bk, nullptr, 1.0f,    1, 0);
    gemm_bias_kernel<<<ggrid, 256>>>(x, Wv, bv, nullptr, 1.0f,    2, 0);

    // attention per (col, head)
    size_t smem = (size_t)(2 * 128 * 64 + 128 * 129) * sizeof(float);
    cudaFuncSetAttribute(attn_kernel,
                         cudaFuncAttributeMaxDynamicSharedMemorySize, (int)smem);
    dim3 agrid(NC, NH);
    attn_kernel<<<agrid, 128, smem>>>(pm, probs_out, write_probs);

    // output projection from g_c into d_out
    gemm_bias_kernel<<<ggrid, 256>>>(nullptr, Wo, bo, out, 1.0f, 3, 1);
}

// round 4
// speedup vs baseline: 1.3410x; 1.3410x over previous
#include <cuda_runtime.h>

// Problem constants
static constexpr int NR = 128;    // rows (attention mixes over this axis)
static constexpr int NC = 256;    // cols
static constexpr int NE = 768;    // embed
static constexpr int NH = 12;     // heads
static constexpr int ND = 64;     // head dim
static constexpr int NTOK = NR * NC;          // 32768 tokens
static constexpr int OUT_ELEMS = NTOK * NE;   // 25165824
static constexpr float SCALING = 0.125f;      // 1/sqrt(64)

// Scratch (allocation-free rule: __device__ globals)
__device__ float g_q[NTOK * NE];
__device__ float g_k[NTOK * NE];
__device__ float g_v[NTOK * NE];
__device__ float g_c[NTOK * NE];

__device__ __forceinline__ unsigned f2tf32(float f) {
    unsigned u;
    asm("cvt.rna.tf32.f32 %0, %1;" : "=r"(u) : "f"(f));
    return u;
}

// ---------------------------------------------------------------------------
// TF32 tensor-core GEMM: out[m][n] = scale * ( sum_k X[m][k]*W[n][k] + bias[n] )
// M=32768, N=768, K=768, both operands K-contiguous (row.col mma layout).
// BM=128, BN=64, BK=32. 256 threads = 8 warps (4m x 2n), warp tile 32x32,
// mma.sync.aligned.m16n8k8.row.col.f32.tf32.tf32.f32, 2x4 tiles per warp.
// Grid is (N/64, M/128) so consecutive blocks share the same A panel (L2 reuse).
// out_sel: 0->g_q, 1->g_k, 2->g_v, 3->'out' param.  in_sel: 0->'X', 1->g_c.
// ---------------------------------------------------------------------------
__global__ __launch_bounds__(256) void gemm_tf32_kernel(
    const float* __restrict__ X, const float* __restrict__ W,
    const float* __restrict__ bias, float* __restrict__ out,
    float scale, int out_sel, int in_sel)
{
    if (in_sel == 1) X = g_c;
    if (out_sel == 0) out = g_q;
    else if (out_sel == 1) out = g_k;
    else if (out_sel == 2) out = g_v;

    // stride 136 / 72: both ≡ 8 (mod 32) -> conflict-free fragment loads
    __shared__ unsigned As[32][136];   // [k][m], tf32 bit patterns
    __shared__ unsigned Bs[32][72];    // [k][n]

    const int tid  = threadIdx.x;
    const int warp = tid >> 5;
    const int lane = tid & 31;
    const int gid  = lane >> 2;        // 0..7
    const int tig  = lane & 3;         // 0..3
    const int wm   = warp >> 1;        // 0..3  -> m offset wm*32
    const int wn   = warp & 1;         // 0..1  -> n offset wn*32

    const int bn = blockIdx.x * 64;
    const int bm = blockIdx.y * 128;

    float acc[2][4][4];
    #pragma unroll
    for (int mi = 0; mi < 2; mi++)
        #pragma unroll
        for (int ni = 0; ni < 4; ni++)
            #pragma unroll
            for (int r = 0; r < 4; r++) acc[mi][ni][r] = 0.0f;

    // global-load indices (coalesced per-thread 64B / 32B chunks)
    const int am   = tid & 127;             // A row within tile
    const int akseg = (tid >> 7) * 16;      // 0 or 16
    const int brow = tid & 63;              // B row within tile
    const int bkseg = (tid >> 6) * 8;       // 0,8,16,24

    for (int k0 = 0; k0 < NE; k0 += 32) {
        // A tile: 128 x 32
        {
            const float* src = X + (size_t)(bm + am) * NE + k0 + akseg;
            #pragma unroll
            for (int q = 0; q < 4; q++) {
                float4 v = *(const float4*)(src + 4 * q);
                As[akseg + 4 * q + 0][am] = f2tf32(v.x);
                As[akseg + 4 * q + 1][am] = f2tf32(v.y);
                As[akseg + 4 * q + 2][am] = f2tf32(v.z);
                As[akseg + 4 * q + 3][am] = f2tf32(v.w);
            }
        }
        // B tile: 64 x 32
        {
            const float* src = W + (size_t)(bn + brow) * NE + k0 + bkseg;
            #pragma unroll
            for (int q = 0; q < 2; q++) {
                float4 v = *(const float4*)(src + 4 * q);
                Bs[bkseg + 4 * q + 0][brow] = f2tf32(v.x);
                Bs[bkseg + 4 * q + 1][brow] = f2tf32(v.y);
                Bs[bkseg + 4 * q + 2][brow] = f2tf32(v.z);
                Bs[bkseg + 4 * q + 3][brow] = f2tf32(v.w);
            }
        }
        __syncthreads();

        #pragma unroll
        for (int ks = 0; ks < 32; ks += 8) {
            unsigned a[2][4], b[4][2];
            #pragma unroll
            for (int mi = 0; mi < 2; mi++) {
                int m0 = wm * 32 + mi * 16;
                a[mi][0] = As[ks + tig    ][m0 + gid];
                a[mi][1] = As[ks + tig    ][m0 + gid + 8];
                a[mi][2] = As[ks + tig + 4][m0 + gid];
                a[mi][3] = As[ks + tig + 4][m0 + gid + 8];
            }
            #pragma unroll
            for (int ni = 0; ni < 4; ni++) {
                int n0 = wn * 32 + ni * 8;
                b[ni][0] = Bs[ks + tig    ][n0 + gid];
                b[ni][1] = Bs[ks + tig + 4][n0 + gid];
            }
            #pragma unroll
            for (int mi = 0; mi < 2; mi++)
                #pragma unroll
                for (int ni = 0; ni < 4; ni++) {
                    asm volatile(
                        "mma.sync.aligned.m16n8k8.row.col.f32.tf32.tf32.f32 "
                        "{%0,%1,%2,%3}, {%4,%5,%6,%7}, {%8,%9}, {%0,%1,%2,%3};"
                        : "+f"(acc[mi][ni][0]), "+f"(acc[mi][ni][1]),
                          "+f"(acc[mi][ni][2]), "+f"(acc[mi][ni][3])
                        : "r"(a[mi][0]), "r"(a[mi][1]),
                          "r"(a[mi][2]), "r"(a[mi][3]),
                          "r"(b[ni][0]), "r"(b[ni][1]));
                }
        }
        __syncthreads();
    }

    // epilogue: c0,c1 -> (row gid, cols tig*2, tig*2+1); c2,c3 -> row gid+8
    #pragma unroll
    for (int mi = 0; mi < 2; mi++) {
        int m_base = bm + wm * 32 + mi * 16;
        #pragma unroll
        for (int ni = 0; ni < 4; ni++) {
            int n = bn + wn * 32 + ni * 8 + tig * 2;
            float2 bv = *(const float2*)&bias[n];
            float2 o0, o1;
            o0.x = scale * (acc[mi][ni][0] + bv.x);
            o0.y = scale * (acc[mi][ni][1] + bv.y);
            o1.x = scale * (acc[mi][ni][2] + bv.x);
            o1.y = scale * (acc[mi][ni][3] + bv.y);
            *(float2*)&out[(size_t)(m_base + gid    ) * NE + n] = o0;
            *(float2*)&out[(size_t)(m_base + gid + 8) * NE + n] = o1;
        }
    }
}

// ---------------------------------------------------------------------------
// Attention: one block per (col c, head h). 128 threads, thread i = query row i.
// Dynamic smem: ks[128*64] | vs[128*64] | Ps[128*129]
// ---------------------------------------------------------------------------
__global__ __launch_bounds__(128) void attn_kernel(
    const unsigned char* __restrict__ mask, float* __restrict__ probs_out,
    int write_probs)
{
    extern __shared__ float sm[];
    float* ks = sm;                 // [128][64]
    float* vs = sm + 128 * 64;      // [128][64]
    float* Ps = sm + 2 * 128 * 64;  // [128][129]  (pad 1 -> conflict-free)
    __shared__ unsigned char msk[128];

    const int c = blockIdx.x;
    const int h = blockIdx.y;
    const int tid = threadIdx.x;
    const int i = tid;

    msk[tid] = mask[tid * NC + c];

    for (int f = tid; f < 128 * 16; f += 128) {
        int j = f >> 4, u = f & 15;
        size_t g = ((size_t)(j * NC + c)) * NE + h * ND + u * 4;
        *(float4*)&ks[j * 64 + u * 4] = *(const float4*)&g_k[g];
        *(float4*)&vs[j * 64 + u * 4] = *(const float4*)&g_v[g];
    }

    float4 q4[16];
    {
        size_t g = ((size_t)(i * NC + c)) * NE + h * ND;
        #pragma unroll
        for (int u = 0; u < 16; u++)
            q4[u] = *(const float4*)&g_q[g + u * 4];
    }
    __syncthreads();

    float maxv = -1e30f;
    for (int j = 0; j < 128; j++) {
        float acc = 0.0f;
        #pragma unroll
        for (int u = 0; u < 16; u++) {
            float4 kv = *(const float4*)&ks[j * 64 + u * 4];
            acc += q4[u].x * kv.x + q4[u].y * kv.y
                 + q4[u].z * kv.z + q4[u].w * kv.w;
        }
        if (msk[j]) acc = -10000.0f;
        Ps[i * 129 + j] = acc;
        maxv = fmaxf(maxv, acc);
    }

    float sum = 0.0f;
    for (int j = 0; j < 128; j++) {
        float e = __expf(Ps[i * 129 + j] - maxv);
        Ps[i * 129 + j] = e;
        sum += e;
    }
    float inv = 1.0f / sum;
    for (int j = 0; j < 128; j++) Ps[i * 129 + j] *= inv;

    __syncthreads();

    if (write_probs) {
        float* dst = probs_out + ((size_t)(h * NC + c)) * NR * NR;
        for (int f = tid; f < 128 * 32; f += 128) {
            int row = f >> 5, u = f & 31;
            const float* src = &Ps[row * 129 + u * 4];
            float4 pv = make_float4(src[0], src[1], src[2], src[3]);
            *(float4*)&dst[row * 128 + u * 4] = pv;
        }
    }

    float4 a4[16];
    #pragma unroll
    for (int u = 0; u < 16; u++) a4[u] = make_float4(0.f, 0.f, 0.f, 0.f);
    for (int j = 0; j < 128; j++) {
        float p = Ps[i * 129 + j];
        #pragma unroll
        for (int u = 0; u < 16; u++) {
            float4 vv = *(const float4*)&vs[j * 64 + u * 4];
            a4[u].x += p * vv.x; a4[u].y += p * vv.y;
            a4[u].z += p * vv.z; a4[u].w += p * vv.w;
        }
    }
    {
        size_t g = ((size_t)(i * NC + c)) * NE + h * ND;
        #pragma unroll
        for (int u = 0; u < 16; u++)
            *(float4*)&g_c[g + u * 4] = a4[u];
    }
}

// ---------------------------------------------------------------------------
extern "C" void kernel_launch(void* const* d_in, const int* in_sizes, int n_in,
                              void* d_out, int out_size)
{
    const float* x          = (const float*)d_in[0];
    const unsigned char* pm = (const unsigned char*)d_in[1];
    const float* Wq = (const float*)d_in[2];
    const float* bq = (const float*)d_in[3];
    const float* Wk = (const float*)d_in[4];
    const float* bk = (const float*)d_in[5];
    const float* Wv = (const float*)d_in[6];
    const float* bv = (const float*)d_in[7];
    const float* Wo = (const float*)d_in[8];
    const float* bo = (const float*)d_in[9];
    float* out = (float*)d_out;

    const int write_probs = (out_size > OUT_ELEMS) ? 1 : 0;
    float* probs_out = out + OUT_ELEMS;

    dim3 ggrid(NE / 64, NTOK / 128);   // n-fastest: A-panel L2 reuse
    gemm_tf32_kernel<<<ggrid, 256>>>(x, Wq, bq, nullptr, SCALING, 0, 0);
    gemm_tf32_kernel<<<ggrid, 256>>>(x, Wk, bk, nullptr, 1.0f,    1, 0);
    gemm_tf32_kernel<<<ggrid, 256>>>(x, Wv, bv, nullptr, 1.0f,    2, 0);

    size_t smem = (size_t)(2 * 128 * 64 + 128 * 129) * sizeof(float);
    cudaFuncSetAttribute(attn_kernel,
                         cudaFuncAttributeMaxDynamicSharedMemorySize, (int)smem);
    dim3 agrid(NC, NH);
    attn_kernel<<<agrid, 128, smem>>>(pm, probs_out, write_probs);

    gemm_tf32_kernel<<<ggrid, 256>>>(nullptr, Wo, bo, out, 1.0f, 3, 1);
}